// round 2
// baseline (speedup 1.0000x reference)
#include <cuda_runtime.h>
#include <math.h>

#define N_NODES 50000
#define N_EDGES 800000
#define F_NODE  92
#define F_EDGE  50
#define HID     128

// ---------------- scratch (static device globals; no runtime allocation) ----
__device__ float g_h[N_NODES * HID];          // node features
__device__ float g_Afi[N_NODES * HID];
__device__ float g_Afj[N_NODES * HID];
__device__ float g_Asi[N_NODES * HID];
__device__ float g_Asj[N_NODES * HID];
__device__ float g_EF[N_EDGES * HID];
__device__ float g_ES[N_EDGES * HID];
__device__ float g_agg[N_NODES * HID];

// ---------------- generic tiled GEMM: C = act(A[M,K] @ B[K,N] (+bias)) ------
#define BM 128
#define BN 128
#define BKK 16
#define TM 8
#define TN 8

template<int ACT>  // 0 = none, 1 = relu
__global__ __launch_bounds__(256)
void gemm_kernel(const float* __restrict__ A, const float* __restrict__ B,
                 const float* __restrict__ bias, float* __restrict__ C,
                 int M, int N, int K)
{
    __shared__ float As[BKK][BM + 4];
    __shared__ float Bs[BKK][BN + 4];

    const int tid  = threadIdx.x;
    const int bx   = blockIdx.x;
    const int by   = blockIdx.y;
    const int tcol = tid & 15;   // 0..15
    const int trow = tid >> 4;   // 0..15
    const int row0 = by * BM;
    const int col0 = bx * BN;

    float acc[TM][TN];
#pragma unroll
    for (int i = 0; i < TM; i++)
#pragma unroll
        for (int j = 0; j < TN; j++) acc[i][j] = 0.f;

    for (int k0 = 0; k0 < K; k0 += BKK) {
        // load A tile (BM x BKK), transposed into As[k][m]
#pragma unroll
        for (int i = 0; i < (BM * BKK) / 256; i++) {
            int idx = tid + i * 256;
            int r = idx >> 4;          // /BKK
            int c = idx & 15;          // %BKK
            int gr = row0 + r, gc = k0 + c;
            float v = 0.f;
            if (gr < M && gc < K) v = A[(long long)gr * K + gc];
            As[c][r] = v;
        }
        // load B tile (BKK x BN)
#pragma unroll
        for (int i = 0; i < (BKK * BN) / 256; i++) {
            int idx = tid + i * 256;
            int r = idx >> 7;          // /BN
            int c = idx & 127;         // %BN
            int gr = k0 + r, gc = col0 + c;
            float v = 0.f;
            if (gr < K && gc < N) v = B[(long long)gr * N + gc];
            Bs[r][c] = v;
        }
        __syncthreads();

#pragma unroll
        for (int kk = 0; kk < BKK; kk++) {
            float a[TM], b[TN];
#pragma unroll
            for (int i = 0; i < TM; i++) a[i] = As[kk][trow * TM + i];
#pragma unroll
            for (int j = 0; j < TN; j++) b[j] = Bs[kk][tcol * TN + j];
#pragma unroll
            for (int i = 0; i < TM; i++)
#pragma unroll
                for (int j = 0; j < TN; j++)
                    acc[i][j] = fmaf(a[i], b[j], acc[i][j]);
        }
        __syncthreads();
    }

#pragma unroll
    for (int i = 0; i < TM; i++) {
        int gr = row0 + trow * TM + i;
        if (gr < M) {
#pragma unroll
            for (int j = 0; j < TN; j++) {
                int gc = col0 + tcol * TN + j;
                if (gc < N) {
                    float v = acc[i][j];
                    if (bias) v += bias[gc];
                    if (ACT == 1) v = fmaxf(v, 0.f);
                    C[(long long)gr * N + gc] = v;
                }
            }
        }
    }
}

// ---------------- copy kernel (agg = h) -------------------------------------
__global__ void copy_kernel(const float* __restrict__ src, float* __restrict__ dst, int n4)
{
    int i = blockIdx.x * blockDim.x + threadIdx.x;
    if (i < n4) reinterpret_cast<float4*>(dst)[i] = reinterpret_cast<const float4*>(src)[i];
}

// ---------------- edge message + scatter ------------------------------------
// pf = EF[e] + Afi[dst] + Afj[src] ; ps = ES[e] + Asi[dst] + Asj[src]
// msg = sigmoid(pf) * softplus(ps) ; agg[dst] += msg
__global__ __launch_bounds__(256)
void edge_msg_kernel(const float* __restrict__ EF, const float* __restrict__ ES,
                     const float* __restrict__ Afi, const float* __restrict__ Afj,
                     const float* __restrict__ Asi, const float* __restrict__ Asj,
                     const int* __restrict__ src_idx,
                     const int* __restrict__ dst_idx,
                     float* __restrict__ agg)
{
    int e = blockIdx.x * 2 + (threadIdx.x >> 7);
    int j = threadIdx.x & 127;
    if (e >= N_EDGES) return;

    int s = src_idx[e];
    int d = dst_idx[e];

    float pf = EF[(long long)e * HID + j] + Afi[d * HID + j] + Afj[s * HID + j];
    float ps = ES[(long long)e * HID + j] + Asi[d * HID + j] + Asj[s * HID + j];

    float sig = 1.f / (1.f + __expf(-pf));
    // softplus = max(x,0) + log1p(exp(-|x|))
    float sp  = fmaxf(ps, 0.f) + log1pf(__expf(-fabsf(ps)));

    atomicAdd(&agg[d * HID + j], sig * sp);
}

// ---------------- launch -----------------------------------------------------
static inline void gemm_launch(int act, const float* A, const float* B,
                               const float* bias, float* C, int M, int N, int K)
{
    dim3 grid((N + BN - 1) / BN, (M + BM - 1) / BM);
    if (act == 1) gemm_kernel<1><<<grid, 256>>>(A, B, bias, C, M, N, K);
    else          gemm_kernel<0><<<grid, 256>>>(A, B, bias, C, M, N, K);
}

extern "C" void kernel_launch(void* const* d_in, const int* in_sizes, int n_in,
                              void* d_out, int out_size)
{
    const float* x         = (const float*)d_in[0];   // [50000, 92]
    const float* edge_attr = (const float*)d_in[1];   // [800000, 50]
    const float* W_in      = (const float*)d_in[2];   // [92, 128]
    const float* b_in      = (const float*)d_in[3];   // [128]
    const float* Wf        = (const float*)d_in[4];   // [2, 306, 128]
    const float* bf        = (const float*)d_in[5];   // [2, 128]
    const float* Ws        = (const float*)d_in[6];   // [2, 306, 128]
    const float* bs        = (const float*)d_in[7];   // [2, 128]
    const float* Wm        = (const float*)d_in[8];   // [2, 128, 128]
    const float* bm        = (const float*)d_in[9];   // [2, 128]
    const int*   ei        = (const int*)d_in[10];    // [2, 800000] int32 (JAX x64 off)
    float* out = (float*)d_out;

    const int* src = ei;
    const int* dst = ei + N_EDGES;

    float* h;    cudaGetSymbolAddress((void**)&h,    g_h);
    float* Afi;  cudaGetSymbolAddress((void**)&Afi,  g_Afi);
    float* Afj;  cudaGetSymbolAddress((void**)&Afj,  g_Afj);
    float* Asi;  cudaGetSymbolAddress((void**)&Asi,  g_Asi);
    float* Asj;  cudaGetSymbolAddress((void**)&Asj,  g_Asj);
    float* EF;   cudaGetSymbolAddress((void**)&EF,   g_EF);
    float* ES;   cudaGetSymbolAddress((void**)&ES,   g_ES);
    float* agg;  cudaGetSymbolAddress((void**)&agg,  g_agg);

    // h = relu(x @ W_in + b_in)
    gemm_launch(1, x, W_in, b_in, h, N_NODES, HID, F_NODE);

    for (int l = 0; l < 2; l++) {
        const float* Wfl = Wf + (long long)l * 306 * HID;
        const float* Wsl = Ws + (long long)l * 306 * HID;
        const float* bfl = bf + l * HID;
        const float* bsl = bs + l * HID;
        const float* Wml = Wm + (long long)l * HID * HID;
        const float* bml = bm + l * HID;

        // node projections: h @ Wf_i / Wf_j / Ws_i / Ws_j
        gemm_launch(0, h, Wfl,              nullptr, Afi, N_NODES, HID, HID);
        gemm_launch(0, h, Wfl + 128 * HID,  nullptr, Afj, N_NODES, HID, HID);
        gemm_launch(0, h, Wsl,              nullptr, Asi, N_NODES, HID, HID);
        gemm_launch(0, h, Wsl + 128 * HID,  nullptr, Asj, N_NODES, HID, HID);

        // edge projections: edge_attr @ Wf_e + bf, edge_attr @ Ws_e + bs
        gemm_launch(0, edge_attr, Wfl + 256 * HID, bfl, EF, N_EDGES, HID, F_EDGE);
        gemm_launch(0, edge_attr, Wsl + 256 * HID, bsl, ES, N_EDGES, HID, F_EDGE);

        // agg = h  (so that after scatter, agg = h + segment_sum(msg))
        {
            int n4 = (N_NODES * HID) / 4;
            copy_kernel<<<(n4 + 255) / 256, 256>>>(h, agg, n4);
        }

        // edge messages + scatter-add
        edge_msg_kernel<<<N_EDGES / 2, 256>>>(EF, ES, Afi, Afj, Asi, Asj, src, dst, agg);

        // h = relu(agg @ Wm + bm)  -> final layer writes straight to d_out
        float* hout = (l == 1) ? out : h;
        gemm_launch(1, agg, Wml, bml, hout, N_NODES, HID, HID);
    }
}

// round 3
// speedup vs baseline: 1.2819x; 1.2819x over previous
#include <cuda_runtime.h>
#include <math.h>

#define N_NODES 50000
#define N_EDGES 800000
#define F_NODE  92
#define F_EDGE  50
#define HID     128

// ---------------- scratch (static device globals) ---------------------------
__device__ float g_h[N_NODES * HID];            // node features
__device__ float g_Apack[N_NODES * 4 * HID];    // [node][512]: Afi|Afj|Asi|Asj
__device__ float g_agg[N_NODES * HID];
__device__ float g_Wpack[2 * HID * 4 * HID];    // per-layer packed proj weights [128][512]

// ---------------- generic tiled GEMM: C = act(A[M,K] @ B[K,N] (+bias)) ------
#define BM 128
#define BN 128
#define BKK 16
#define TM 8
#define TN 8

template<int ACT>  // 0 = none, 1 = relu
__global__ __launch_bounds__(256)
void gemm_kernel(const float* __restrict__ A, const float* __restrict__ B,
                 const float* __restrict__ bias, float* __restrict__ C,
                 int M, int N, int K)
{
    __shared__ float As[BKK][BM + 4];
    __shared__ float Bs[BKK][BN + 4];

    const int tid  = threadIdx.x;
    const int bx   = blockIdx.x;
    const int by   = blockIdx.y;
    const int tcol = tid & 15;
    const int trow = tid >> 4;
    const int row0 = by * BM;
    const int col0 = bx * BN;

    float acc[TM][TN];
#pragma unroll
    for (int i = 0; i < TM; i++)
#pragma unroll
        for (int j = 0; j < TN; j++) acc[i][j] = 0.f;

    for (int k0 = 0; k0 < K; k0 += BKK) {
#pragma unroll
        for (int i = 0; i < (BM * BKK) / 256; i++) {
            int idx = tid + i * 256;
            int r = idx >> 4;
            int c = idx & 15;
            int gr = row0 + r, gc = k0 + c;
            float v = 0.f;
            if (gr < M && gc < K) v = A[(long long)gr * K + gc];
            As[c][r] = v;
        }
#pragma unroll
        for (int i = 0; i < (BKK * BN) / 256; i++) {
            int idx = tid + i * 256;
            int r = idx >> 7;
            int c = idx & 127;
            int gr = k0 + r, gc = col0 + c;
            float v = 0.f;
            if (gr < K && gc < N) v = B[(long long)gr * N + gc];
            Bs[r][c] = v;
        }
        __syncthreads();

#pragma unroll
        for (int kk = 0; kk < BKK; kk++) {
            float a[TM], b[TN];
#pragma unroll
            for (int i = 0; i < TM; i++) a[i] = As[kk][trow * TM + i];
#pragma unroll
            for (int j = 0; j < TN; j++) b[j] = Bs[kk][tcol * TN + j];
#pragma unroll
            for (int i = 0; i < TM; i++)
#pragma unroll
                for (int j = 0; j < TN; j++)
                    acc[i][j] = fmaf(a[i], b[j], acc[i][j]);
        }
        __syncthreads();
    }

#pragma unroll
    for (int i = 0; i < TM; i++) {
        int gr = row0 + trow * TM + i;
        if (gr < M) {
#pragma unroll
            for (int j = 0; j < TN; j++) {
                int gc = col0 + tcol * TN + j;
                if (gc < N) {
                    float v = acc[i][j];
                    if (bias) v += bias[gc];
                    if (ACT == 1) v = fmaxf(v, 0.f);
                    C[(long long)gr * N + gc] = v;
                }
            }
        }
    }
}

// ---------------- weight pack: Wpack[l][k][c] --------------------------------
// c in [0,128): Wf[l][k][j]      (Wf_i)
// c in [128,256): Wf[l][128+k][j] (Wf_j)
// c in [256,384): Ws[l][k][j]     (Ws_i)
// c in [384,512): Ws[l][128+k][j] (Ws_j)
__global__ void pack_weights_kernel(const float* __restrict__ Wf,
                                    const float* __restrict__ Ws,
                                    float* __restrict__ Wpack)
{
    int idx = blockIdx.x * 256 + threadIdx.x;   // l*65536 + k*512 + c
    if (idx >= 2 * 128 * 512) return;
    int l = idx >> 16;
    int k = (idx >> 9) & 127;
    int c = idx & 511;
    int sel = c >> 7;
    int j = c & 127;
    const float* W = (sel < 2) ? Wf : Ws;
    int row = (sel & 1) ? (128 + k) : k;
    Wpack[idx] = W[(long long)l * 306 * 128 + row * 128 + j];
}

// ---------------- copy kernel (agg = h) --------------------------------------
__global__ void copy_kernel(const float* __restrict__ src, float* __restrict__ dst, int n4)
{
    int i = blockIdx.x * blockDim.x + threadIdx.x;
    if (i < n4) reinterpret_cast<float4*>(dst)[i] = reinterpret_cast<const float4*>(src)[i];
}

// ---------------- fused edge kernel ------------------------------------------
// Per block: TE edges. Shared: Wf_e[50][128], Ws_e[50][128], ea[TE][50].
// For edge e, hid j:
//   pf = (ea[e] . Wf_e[:,j]) + bf[j] + Apack[d][j]     + Apack[s][128+j]
//   ps = (ea[e] . Ws_e[:,j]) + bs[j] + Apack[d][256+j] + Apack[s][384+j]
//   agg[d][j] += sigmoid(pf) * softplus(ps)
#define TE 128

__global__ __launch_bounds__(256)
void edge_fused_kernel(const float* __restrict__ edge_attr,
                       const float* __restrict__ Wfe,   // [50][128]
                       const float* __restrict__ Wse,   // [50][128]
                       const float* __restrict__ bf_l,
                       const float* __restrict__ bs_l,
                       const float* __restrict__ Apack, // [N_NODES][512]
                       const int* __restrict__ src_idx,
                       const int* __restrict__ dst_idx,
                       float* __restrict__ agg)
{
    extern __shared__ float sm[];
    float* Wf_s = sm;                 // 6400 floats
    float* Ws_s = sm + 6400;          // 6400 floats
    float* ea_s = sm + 12800;         // TE*50 floats

    const int tid  = threadIdx.x;
    const int lane = tid & 31;
    const int warp = tid >> 5;
    const int e0   = blockIdx.x * TE;

    // load weights (float4, coalesced)
    {
        const float4* wf4 = reinterpret_cast<const float4*>(Wfe);
        const float4* ws4 = reinterpret_cast<const float4*>(Wse);
        float4* sf4 = reinterpret_cast<float4*>(Wf_s);
        float4* ss4 = reinterpret_cast<float4*>(Ws_s);
#pragma unroll
        for (int i = 0; i < 1600 / 256 + 1; i++) {
            int idx = tid + i * 256;
            if (idx < 1600) { sf4[idx] = wf4[idx]; ss4[idx] = ws4[idx]; }
        }
    }
    // load edge_attr tile (scalar, coalesced)
    {
        const float* gbase = edge_attr + (long long)e0 * F_EDGE;
#pragma unroll
        for (int i = 0; i < (TE * F_EDGE) / 256; i++) {
            int idx = tid + i * 256;
            ea_s[idx] = gbase[idx];
        }
    }
    __syncthreads();

    const float4 bf4 = *reinterpret_cast<const float4*>(bf_l + lane * 4);
    const float4 bs4 = *reinterpret_cast<const float4*>(bs_l + lane * 4);

#pragma unroll 1
    for (int i = 0; i < TE / 8; i++) {
        const int el = warp * (TE / 8) + i;
        const int e  = e0 + el;
        const int s  = src_idx[e];
        const int d  = dst_idx[e];

        float4 accf = bf4;
        float4 accs = bs4;

        const float* ea = &ea_s[el * F_EDGE];
#pragma unroll
        for (int k = 0; k < F_EDGE; k++) {
            const float a = ea[k];
            const float4 wf = *reinterpret_cast<const float4*>(&Wf_s[k * 128 + lane * 4]);
            const float4 ws = *reinterpret_cast<const float4*>(&Ws_s[k * 128 + lane * 4]);
            accf.x = fmaf(a, wf.x, accf.x);
            accf.y = fmaf(a, wf.y, accf.y);
            accf.z = fmaf(a, wf.z, accf.z);
            accf.w = fmaf(a, wf.w, accf.w);
            accs.x = fmaf(a, ws.x, accs.x);
            accs.y = fmaf(a, ws.y, accs.y);
            accs.z = fmaf(a, ws.z, accs.z);
            accs.w = fmaf(a, ws.w, accs.w);
        }

        const float4 afi = *reinterpret_cast<const float4*>(&Apack[(long long)d * 512 + lane * 4]);
        const float4 afj = *reinterpret_cast<const float4*>(&Apack[(long long)s * 512 + 128 + lane * 4]);
        const float4 asi = *reinterpret_cast<const float4*>(&Apack[(long long)d * 512 + 256 + lane * 4]);
        const float4 asj = *reinterpret_cast<const float4*>(&Apack[(long long)s * 512 + 384 + lane * 4]);

        float pf0 = accf.x + afi.x + afj.x;
        float pf1 = accf.y + afi.y + afj.y;
        float pf2 = accf.z + afi.z + afj.z;
        float pf3 = accf.w + afi.w + afj.w;
        float ps0 = accs.x + asi.x + asj.x;
        float ps1 = accs.y + asi.y + asj.y;
        float ps2 = accs.z + asi.z + asj.z;
        float ps3 = accs.w + asi.w + asj.w;

        float m0 = (1.f / (1.f + __expf(-pf0))) * (fmaxf(ps0, 0.f) + log1pf(__expf(-fabsf(ps0))));
        float m1 = (1.f / (1.f + __expf(-pf1))) * (fmaxf(ps1, 0.f) + log1pf(__expf(-fabsf(ps1))));
        float m2 = (1.f / (1.f + __expf(-pf2))) * (fmaxf(ps2, 0.f) + log1pf(__expf(-fabsf(ps2))));
        float m3 = (1.f / (1.f + __expf(-pf3))) * (fmaxf(ps3, 0.f) + log1pf(__expf(-fabsf(ps3))));

        float* aout = &agg[(long long)d * HID + lane * 4];
        atomicAdd(aout + 0, m0);
        atomicAdd(aout + 1, m1);
        atomicAdd(aout + 2, m2);
        atomicAdd(aout + 3, m3);
    }
}

// ---------------- launch ------------------------------------------------------
static inline void gemm_launch(int act, const float* A, const float* B,
                               const float* bias, float* C, int M, int N, int K)
{
    dim3 grid((N + BN - 1) / BN, (M + BM - 1) / BM);
    if (act == 1) gemm_kernel<1><<<grid, 256>>>(A, B, bias, C, M, N, K);
    else          gemm_kernel<0><<<grid, 256>>>(A, B, bias, C, M, N, K);
}

extern "C" void kernel_launch(void* const* d_in, const int* in_sizes, int n_in,
                              void* d_out, int out_size)
{
    const float* x         = (const float*)d_in[0];
    const float* edge_attr = (const float*)d_in[1];
    const float* W_in      = (const float*)d_in[2];
    const float* b_in      = (const float*)d_in[3];
    const float* Wf        = (const float*)d_in[4];
    const float* bf        = (const float*)d_in[5];
    const float* Ws        = (const float*)d_in[6];
    const float* bs        = (const float*)d_in[7];
    const float* Wm        = (const float*)d_in[8];
    const float* bm        = (const float*)d_in[9];
    const int*   ei        = (const int*)d_in[10];   // int32
    float* out = (float*)d_out;

    const int* src = ei;
    const int* dst = ei + N_EDGES;

    float* h;     cudaGetSymbolAddress((void**)&h,     g_h);
    float* Apack; cudaGetSymbolAddress((void**)&Apack, g_Apack);
    float* agg;   cudaGetSymbolAddress((void**)&agg,   g_agg);
    float* Wpack; cudaGetSymbolAddress((void**)&Wpack, g_Wpack);

    // allow >48KB dynamic smem for the fused edge kernel
    static bool smem_set = false;
    const int EDGE_SMEM = (6400 + 6400 + TE * F_EDGE) * 4;  // 76800 B
    if (!smem_set) {
        cudaFuncSetAttribute(edge_fused_kernel,
                             cudaFuncAttributeMaxDynamicSharedMemorySize, EDGE_SMEM);
        smem_set = true;
    }

    // pack projection weights for both layers
    pack_weights_kernel<<<(2 * 128 * 512 + 255) / 256, 256>>>(Wf, Ws, Wpack);

    // h = relu(x @ W_in + b_in)
    gemm_launch(1, x, W_in, b_in, h, N_NODES, HID, F_NODE);

    for (int l = 0; l < 2; l++) {
        const float* Wfl = Wf + (long long)l * 306 * HID;
        const float* Wsl = Ws + (long long)l * 306 * HID;
        const float* bfl = bf + l * HID;
        const float* bsl = bs + l * HID;
        const float* Wml = Wm + (long long)l * HID * HID;
        const float* bml = bm + l * HID;
        const float* Wpl = Wpack + (long long)l * 128 * 512;

        // all 4 node projections in one GEMM: Apack = h @ Wpack_l  [50000 x 512]
        gemm_launch(0, h, Wpl, nullptr, Apack, N_NODES, 4 * HID, HID);

        // agg = h
        {
            int n4 = (N_NODES * HID) / 4;
            copy_kernel<<<(n4 + 255) / 256, 256>>>(h, agg, n4);
        }

        // fused: edge projection + message + scatter-add
        edge_fused_kernel<<<N_EDGES / TE, 256, EDGE_SMEM>>>(
            edge_attr, Wfl + 256 * HID, Wsl + 256 * HID, bfl, bsl,
            Apack, src, dst, agg);

        // h = relu(agg @ Wm + bm); final layer writes to d_out
        float* hout = (l == 1) ? out : h;
        gemm_launch(1, agg, Wml, bml, hout, N_NODES, HID, HID);
    }
}

// round 4
// speedup vs baseline: 2.3662x; 1.8458x over previous
#include <cuda_runtime.h>
#include <math.h>

#define N_NODES 50000
#define N_EDGES 800000
#define F_NODE  92
#define F_EDGE  50
#define HID     128

// ---------------- scratch (static device globals) ---------------------------
__device__ float g_h[N_NODES * HID];
__device__ float g_Apack[N_NODES * 4 * HID];    // [node][512]: Afi|Afj|Asi|Asj
__device__ float g_agg[N_NODES * HID];
__device__ float g_Wpack[2 * HID * 4 * HID];    // packed proj weights [l][128][512]

// ---------------- tf32 helpers ----------------------------------------------
__device__ __forceinline__ unsigned f2tf32(float f) {
    unsigned u;
    asm("cvt.rna.tf32.f32 %0, %1;" : "=r"(u) : "f"(f));
    return u;
}

__device__ __forceinline__ void mma_tf32(float& d0, float& d1, float& d2, float& d3,
                                         unsigned a0, unsigned a1, unsigned a2, unsigned a3,
                                         unsigned b0, unsigned b1)
{
    asm volatile(
        "mma.sync.aligned.m16n8k8.row.col.f32.tf32.tf32.f32 "
        "{%0,%1,%2,%3}, {%4,%5,%6,%7}, {%8,%9}, {%0,%1,%2,%3};"
        : "+f"(d0), "+f"(d1), "+f"(d2), "+f"(d3)
        : "r"(a0), "r"(a1), "r"(a2), "r"(a3), "r"(b0), "r"(b1));
}

// ---------------- tf32 tensor-core GEMM: C = act(A[M,K]@B[K,N] (+bias)) ------
// Block tile 128x128, K-chunk 32, 256 threads = 8 warps, warp tile 32x64.
#define GBM 128
#define GBN 128
#define GKC 32

template<int ACT>  // 0 = none, 1 = relu
__global__ __launch_bounds__(256)
void gemm_tf32_kernel(const float* __restrict__ A, const float* __restrict__ B,
                      const float* __restrict__ bias, float* __restrict__ C,
                      int M, int N, int K)
{
    __shared__ float As[GKC][GBM + 1];   // As[k][m], tf32 bits
    __shared__ float Bs[GKC][GBN + 1];   // Bs[k][n], tf32 bits

    const int tid  = threadIdx.x;
    const int lane = tid & 31;
    const int warp = tid >> 5;
    const int g    = lane >> 2;   // groupID 0..7
    const int t    = lane & 3;    // threadID_in_group 0..3

    const int row0 = blockIdx.y * GBM;
    const int col0 = blockIdx.x * GBN;
    const int wr0  = (warp >> 1) * 32;   // warp row offset in tile
    const int wc0  = (warp & 1) * 64;    // warp col offset in tile

    float acc[2][8][4];
#pragma unroll
    for (int m = 0; m < 2; m++)
#pragma unroll
        for (int n = 0; n < 8; n++)
#pragma unroll
            for (int i = 0; i < 4; i++) acc[m][n][i] = 0.f;

    for (int k0 = 0; k0 < K; k0 += GKC) {
        // load A tile (GBM x GKC) -> As[k][m], tf32-converted
#pragma unroll
        for (int i = 0; i < (GBM * GKC) / 256; i++) {
            int idx = tid + i * 256;
            int r = idx >> 5;          // /GKC
            int c = idx & 31;          // %GKC
            int gr = row0 + r, gc = k0 + c;
            float v = 0.f;
            if (gr < M && gc < K) v = A[(long long)gr * K + gc];
            As[c][r] = __uint_as_float(f2tf32(v));
        }
        // load B tile (GKC x GBN) -> Bs[k][n]
#pragma unroll
        for (int i = 0; i < (GKC * GBN) / 256; i++) {
            int idx = tid + i * 256;
            int r = idx >> 7;          // /GBN
            int c = idx & 127;         // %GBN
            int gr = k0 + r, gc = col0 + c;
            float v = 0.f;
            if (gr < K && gc < N) v = B[(long long)gr * N + gc];
            Bs[r][c] = __uint_as_float(f2tf32(v));
        }
        __syncthreads();

#pragma unroll
        for (int kk = 0; kk < GKC / 8; kk++) {
            const int kb = kk * 8;
            unsigned a[2][4];
#pragma unroll
            for (int m = 0; m < 2; m++) {
                int r = wr0 + m * 16;
                a[m][0] = __float_as_uint(As[kb + t    ][r + g    ]);
                a[m][1] = __float_as_uint(As[kb + t    ][r + g + 8]);
                a[m][2] = __float_as_uint(As[kb + t + 4][r + g    ]);
                a[m][3] = __float_as_uint(As[kb + t + 4][r + g + 8]);
            }
#pragma unroll
            for (int n = 0; n < 8; n++) {
                int c = wc0 + n * 8 + g;
                unsigned b0 = __float_as_uint(Bs[kb + t    ][c]);
                unsigned b1 = __float_as_uint(Bs[kb + t + 4][c]);
#pragma unroll
                for (int m = 0; m < 2; m++)
                    mma_tf32(acc[m][n][0], acc[m][n][1], acc[m][n][2], acc[m][n][3],
                             a[m][0], a[m][1], a[m][2], a[m][3], b0, b1);
            }
        }
        __syncthreads();
    }

    // epilogue: c0:(g,2t) c1:(g,2t+1) c2:(g+8,2t) c3:(g+8,2t+1) per 16x8 tile
#pragma unroll
    for (int m = 0; m < 2; m++) {
#pragma unroll
        for (int n = 0; n < 8; n++) {
            int gc = col0 + wc0 + n * 8 + 2 * t;
            float bx = 0.f, by = 0.f;
            if (bias) { bx = bias[gc]; by = bias[gc + 1]; }

            int gr0 = row0 + wr0 + m * 16 + g;
            if (gr0 < M) {
                float v0 = acc[m][n][0] + bx;
                float v1 = acc[m][n][1] + by;
                if (ACT == 1) { v0 = fmaxf(v0, 0.f); v1 = fmaxf(v1, 0.f); }
                *reinterpret_cast<float2*>(&C[(long long)gr0 * N + gc]) = make_float2(v0, v1);
            }
            int gr1 = gr0 + 8;
            if (gr1 < M) {
                float v0 = acc[m][n][2] + bx;
                float v1 = acc[m][n][3] + by;
                if (ACT == 1) { v0 = fmaxf(v0, 0.f); v1 = fmaxf(v1, 0.f); }
                *reinterpret_cast<float2*>(&C[(long long)gr1 * N + gc]) = make_float2(v0, v1);
            }
        }
    }
}

// ---------------- weight pack -------------------------------------------------
__global__ void pack_weights_kernel(const float* __restrict__ Wf,
                                    const float* __restrict__ Ws,
                                    float* __restrict__ Wpack)
{
    int idx = blockIdx.x * 256 + threadIdx.x;   // l*65536 + k*512 + c
    if (idx >= 2 * 128 * 512) return;
    int l = idx >> 16;
    int k = (idx >> 9) & 127;
    int c = idx & 511;
    int sel = c >> 7;
    int j = c & 127;
    const float* W = (sel < 2) ? Wf : Ws;
    int row = (sel & 1) ? (128 + k) : k;
    Wpack[idx] = W[(long long)l * 306 * 128 + row * 128 + j];
}

// ---------------- copy kernel (agg = h) ---------------------------------------
__global__ void copy_kernel(const float* __restrict__ src, float* __restrict__ dst, int n4)
{
    int i = blockIdx.x * blockDim.x + threadIdx.x;
    if (i < n4) reinterpret_cast<float4*>(dst)[i] = reinterpret_cast<const float4*>(src)[i];
}

// ---------------- fused edge kernel (4-edge ILP) -------------------------------
#define TE 128

__global__ __launch_bounds__(256)
void edge_fused_kernel(const float* __restrict__ edge_attr,
                       const float* __restrict__ Wfe,   // [50][128]
                       const float* __restrict__ Wse,   // [50][128]
                       const float* __restrict__ bf_l,
                       const float* __restrict__ bs_l,
                       const float* __restrict__ Apack, // [N_NODES][512]
                       const int* __restrict__ src_idx,
                       const int* __restrict__ dst_idx,
                       float* __restrict__ agg)
{
    extern __shared__ float sm[];
    float* Wf_s = sm;                 // 6400 floats
    float* Ws_s = sm + 6400;          // 6400 floats
    float* ea_s = sm + 12800;         // TE*50 floats

    const int tid  = threadIdx.x;
    const int lane = tid & 31;
    const int warp = tid >> 5;
    const int e0   = blockIdx.x * TE;

    // load weights (float4, coalesced)
    {
        const float4* wf4 = reinterpret_cast<const float4*>(Wfe);
        const float4* ws4 = reinterpret_cast<const float4*>(Wse);
        float4* sf4 = reinterpret_cast<float4*>(Wf_s);
        float4* ss4 = reinterpret_cast<float4*>(Ws_s);
#pragma unroll
        for (int i = 0; i < 7; i++) {
            int idx = tid + i * 256;
            if (idx < 1600) { sf4[idx] = wf4[idx]; ss4[idx] = ws4[idx]; }
        }
    }
    // load edge_attr tile
    {
        const float* gbase = edge_attr + (long long)e0 * F_EDGE;
#pragma unroll
        for (int i = 0; i < (TE * F_EDGE) / 256; i++) {
            int idx = tid + i * 256;
            ea_s[idx] = gbase[idx];
        }
    }
    __syncthreads();

    const float4 bf4 = *reinterpret_cast<const float4*>(bf_l + lane * 4);
    const float4 bs4 = *reinterpret_cast<const float4*>(bs_l + lane * 4);

    // each warp handles 16 edges, 4 at a time (W smem loads amortized over 4 edges)
#pragma unroll 1
    for (int grp = 0; grp < 4; grp++) {
        const int elb = warp * 16 + grp * 4;    // first local edge of this group

        float4 accf[4], accs[4];
#pragma unroll
        for (int q = 0; q < 4; q++) { accf[q] = bf4; accs[q] = bs4; }

        const float* ea0 = &ea_s[(elb + 0) * F_EDGE];
        const float* ea1 = &ea_s[(elb + 1) * F_EDGE];
        const float* ea2 = &ea_s[(elb + 2) * F_EDGE];
        const float* ea3 = &ea_s[(elb + 3) * F_EDGE];

#pragma unroll 2
        for (int k = 0; k < F_EDGE; k++) {
            const float4 wf = *reinterpret_cast<const float4*>(&Wf_s[k * 128 + lane * 4]);
            const float4 ws = *reinterpret_cast<const float4*>(&Ws_s[k * 128 + lane * 4]);
            const float a0 = ea0[k], a1 = ea1[k], a2 = ea2[k], a3 = ea3[k];

            accf[0].x = fmaf(a0, wf.x, accf[0].x); accf[0].y = fmaf(a0, wf.y, accf[0].y);
            accf[0].z = fmaf(a0, wf.z, accf[0].z); accf[0].w = fmaf(a0, wf.w, accf[0].w);
            accf[1].x = fmaf(a1, wf.x, accf[1].x); accf[1].y = fmaf(a1, wf.y, accf[1].y);
            accf[1].z = fmaf(a1, wf.z, accf[1].z); accf[1].w = fmaf(a1, wf.w, accf[1].w);
            accf[2].x = fmaf(a2, wf.x, accf[2].x); accf[2].y = fmaf(a2, wf.y, accf[2].y);
            accf[2].z = fmaf(a2, wf.z, accf[2].z); accf[2].w = fmaf(a2, wf.w, accf[2].w);
            accf[3].x = fmaf(a3, wf.x, accf[3].x); accf[3].y = fmaf(a3, wf.y, accf[3].y);
            accf[3].z = fmaf(a3, wf.z, accf[3].z); accf[3].w = fmaf(a3, wf.w, accf[3].w);

            accs[0].x = fmaf(a0, ws.x, accs[0].x); accs[0].y = fmaf(a0, ws.y, accs[0].y);
            accs[0].z = fmaf(a0, ws.z, accs[0].z); accs[0].w = fmaf(a0, ws.w, accs[0].w);
            accs[1].x = fmaf(a1, ws.x, accs[1].x); accs[1].y = fmaf(a1, ws.y, accs[1].y);
            accs[1].z = fmaf(a1, ws.z, accs[1].z); accs[1].w = fmaf(a1, ws.w, accs[1].w);
            accs[2].x = fmaf(a2, ws.x, accs[2].x); accs[2].y = fmaf(a2, ws.y, accs[2].y);
            accs[2].z = fmaf(a2, ws.z, accs[2].z); accs[2].w = fmaf(a2, ws.w, accs[2].w);
            accs[3].x = fmaf(a3, ws.x, accs[3].x); accs[3].y = fmaf(a3, ws.y, accs[3].y);
            accs[3].z = fmaf(a3, ws.z, accs[3].z); accs[3].w = fmaf(a3, ws.w, accs[3].w);
        }

#pragma unroll
        for (int q = 0; q < 4; q++) {
            const int e = e0 + elb + q;
            const int s = src_idx[e];
            const int d = dst_idx[e];

            const float4 afi = *reinterpret_cast<const float4*>(&Apack[(long long)d * 512 + lane * 4]);
            const float4 afj = *reinterpret_cast<const float4*>(&Apack[(long long)s * 512 + 128 + lane * 4]);
            const float4 asi = *reinterpret_cast<const float4*>(&Apack[(long long)d * 512 + 256 + lane * 4]);
            const float4 asj = *reinterpret_cast<const float4*>(&Apack[(long long)s * 512 + 384 + lane * 4]);

            float pf0 = accf[q].x + afi.x + afj.x;
            float pf1 = accf[q].y + afi.y + afj.y;
            float pf2 = accf[q].z + afi.z + afj.z;
            float pf3 = accf[q].w + afi.w + afj.w;
            float ps0 = accs[q].x + asi.x + asj.x;
            float ps1 = accs[q].y + asi.y + asj.y;
            float ps2 = accs[q].z + asi.z + asj.z;
            float ps3 = accs[q].w + asi.w + asj.w;

            float m0 = (1.f / (1.f + __expf(-pf0))) * (fmaxf(ps0, 0.f) + log1pf(__expf(-fabsf(ps0))));
            float m1 = (1.f / (1.f + __expf(-pf1))) * (fmaxf(ps1, 0.f) + log1pf(__expf(-fabsf(ps1))));
            float m2 = (1.f / (1.f + __expf(-pf2))) * (fmaxf(ps2, 0.f) + log1pf(__expf(-fabsf(ps2))));
            float m3 = (1.f / (1.f + __expf(-pf3))) * (fmaxf(ps3, 0.f) + log1pf(__expf(-fabsf(ps3))));

            float* aout = &agg[(long long)d * HID + lane * 4];
            atomicAdd(aout + 0, m0);
            atomicAdd(aout + 1, m1);
            atomicAdd(aout + 2, m2);
            atomicAdd(aout + 3, m3);
        }
    }
}

// ---------------- launch --------------------------------------------------------
static inline void gemm_launch(int act, const float* A, const float* B,
                               const float* bias, float* C, int M, int N, int K)
{
    dim3 grid((N + GBN - 1) / GBN, (M + GBM - 1) / GBM);
    if (act == 1) gemm_tf32_kernel<1><<<grid, 256>>>(A, B, bias, C, M, N, K);
    else          gemm_tf32_kernel<0><<<grid, 256>>>(A, B, bias, C, M, N, K);
}

extern "C" void kernel_launch(void* const* d_in, const int* in_sizes, int n_in,
                              void* d_out, int out_size)
{
    const float* x         = (const float*)d_in[0];
    const float* edge_attr = (const float*)d_in[1];
    const float* W_in      = (const float*)d_in[2];
    const float* b_in      = (const float*)d_in[3];
    const float* Wf        = (const float*)d_in[4];
    const float* bf        = (const float*)d_in[5];
    const float* Ws        = (const float*)d_in[6];
    const float* bs        = (const float*)d_in[7];
    const float* Wm        = (const float*)d_in[8];
    const float* bm        = (const float*)d_in[9];
    const int*   ei        = (const int*)d_in[10];   // int32
    float* out = (float*)d_out;

    const int* src = ei;
    const int* dst = ei + N_EDGES;

    float* h;     cudaGetSymbolAddress((void**)&h,     g_h);
    float* Apack; cudaGetSymbolAddress((void**)&Apack, g_Apack);
    float* agg;   cudaGetSymbolAddress((void**)&agg,   g_agg);
    float* Wpack; cudaGetSymbolAddress((void**)&Wpack, g_Wpack);

    static bool smem_set = false;
    const int EDGE_SMEM = (6400 + 6400 + TE * F_EDGE) * 4;  // 76800 B
    if (!smem_set) {
        cudaFuncSetAttribute(edge_fused_kernel,
                             cudaFuncAttributeMaxDynamicSharedMemorySize, EDGE_SMEM);
        smem_set = true;
    }

    pack_weights_kernel<<<(2 * 128 * 512 + 255) / 256, 256>>>(Wf, Ws, Wpack);

    // h = relu(x @ W_in + b_in)
    gemm_launch(1, x, W_in, b_in, h, N_NODES, HID, F_NODE);

    for (int l = 0; l < 2; l++) {
        const float* Wfl = Wf + (long long)l * 306 * HID;
        const float* Wsl = Ws + (long long)l * 306 * HID;
        const float* bfl = bf + l * HID;
        const float* bsl = bs + l * HID;
        const float* Wml = Wm + (long long)l * HID * HID;
        const float* bml = bm + l * HID;
        const float* Wpl = Wpack + (long long)l * 128 * 512;

        // all 4 node projections in one GEMM: Apack = h @ Wpack_l  [50000 x 512]
        gemm_launch(0, h, Wpl, nullptr, Apack, N_NODES, 4 * HID, HID);

        // agg = h
        {
            int n4 = (N_NODES * HID) / 4;
            copy_kernel<<<(n4 + 255) / 256, 256>>>(h, agg, n4);
        }

        // fused: edge projection + message + scatter-add
        edge_fused_kernel<<<N_EDGES / TE, 256, EDGE_SMEM>>>(
            edge_attr, Wfl + 256 * HID, Wsl + 256 * HID, bfl, bsl,
            Apack, src, dst, agg);

        // h = relu(agg @ Wm + bm); final layer writes to d_out
        float* hout = (l == 1) ? out : h;
        gemm_launch(1, agg, Wml, bml, hout, N_NODES, HID, HID);
    }
}